// round 15
// baseline (speedup 1.0000x reference)
#include <cuda_runtime.h>
#include <cuda_fp16.h>
#include <cstdint>

// ---------------------------------------------------------------------------
// Problem constants
// ---------------------------------------------------------------------------
#define B_SZ   8192
#define IN_SZ  512
#define OUT_SZ 512
#define GP1    21            // grid_size + 1 coefficients per (o,i)
#define KPI    22            // k-slots per input feature (21 coeff + base)
#define KTOT   (IN_SZ * KPI) // 11264
#define STAGES (KTOT / 64)   // 176 stages of K=64

// Dense-GEMM reformulation:
//   out[b,o] = sum_k A[b,k] * Cmat[o,k],   k = i*22 + j
//   A[b, i*22+j]   = (j==idx: 1-t), (j==idx+1: t), (j==21: silu(xc)), else 0  (fp16)
//   Cmat[o, i*22+j]= (j<21: coeffs[o,i,j]), (j==21: base_w[o,i])               (fp16)
// R14: producer work (A-gen, B cp.async, P cp.async) split evenly over ALL
// 256 threads — halves the post-barrier producer critical path that was
// holding the tensor pipe at 50%.

// ---------------------------------------------------------------------------
// Device scratch (static)
// ---------------------------------------------------------------------------
__device__ __half g_Cmat[(size_t)OUT_SZ * KTOT];   // [o][k], 11.5 MB
__device__ float2 g_P[(size_t)IN_SZ * B_SZ];       // [i][b] : {silu(xc), u}

// ---------------------------------------------------------------------------
// Helpers
// ---------------------------------------------------------------------------
__device__ __forceinline__ uint32_t smem_u32(const void* p) {
    uint32_t a;
    asm("{ .reg .u64 t; cvta.to.shared.u64 t, %1; cvt.u32.u64 %0, t; }" : "=r"(a) : "l"(p));
    return a;
}
__device__ __forceinline__ uint32_t sw128(uint32_t off) { return off ^ ((off >> 3) & 0x70); }

__device__ __forceinline__ void ldsm_x4(uint32_t addr, uint32_t r[4]) {
    asm volatile("ldmatrix.sync.aligned.m8n8.x4.shared.b16 {%0,%1,%2,%3}, [%4];"
                 : "=r"(r[0]), "=r"(r[1]), "=r"(r[2]), "=r"(r[3]) : "r"(addr));
}
__device__ __forceinline__ void mma16816(float d[4], const uint32_t a[4],
                                         uint32_t b0, uint32_t b1) {
    asm volatile("mma.sync.aligned.m16n8k16.row.col.f32.f16.f16.f32 "
                 "{%0,%1,%2,%3}, {%4,%5,%6,%7}, {%8,%9}, {%0,%1,%2,%3};"
                 : "+f"(d[0]), "+f"(d[1]), "+f"(d[2]), "+f"(d[3])
                 : "r"(a[0]), "r"(a[1]), "r"(a[2]), "r"(a[3]), "r"(b0), "r"(b1));
}

// ---------------------------------------------------------------------------
// Prep kernel: fuses params (blocks [0,4096)) and Cmat build (blocks >= 4096).
// ---------------------------------------------------------------------------
#define PARAM_BLOCKS 4096                         // (B/32)*(IN/32)
#define CMAT_BLOCKS  (OUT_SZ * (KTOT / 8) / 256)  // 2816

__global__ void kan_prep(const float* __restrict__ x,
                         const float* __restrict__ coeffs,
                         const float* __restrict__ bw) {
    if (blockIdx.x < PARAM_BLOCKS) {
        __shared__ float tile[32][33];
        const int pb = blockIdx.x;
        const int b0 = (pb & 255) * 32;
        const int i0 = (pb >> 8) * 32;
        const int tx = threadIdx.x & 31;
        const int ty = threadIdx.x >> 5;
#pragma unroll
        for (int r = ty; r < 32; r += 8)
            tile[r][tx] = x[(size_t)(b0 + r) * IN_SZ + i0 + tx];
        __syncthreads();
#pragma unroll
        for (int r = ty; r < 32; r += 8) {
            float xv = tile[tx][r];
            float xc = fminf(1.0f, fmaxf(-1.0f, xv));
            float s  = xc / (1.0f + __expf(-xc));
            float u  = (xc + 1.0f) * 10.0f;
            g_P[(size_t)(i0 + r) * B_SZ + b0 + tx] = make_float2(s, u);
        }
    } else {
        int gch = (blockIdx.x - PARAM_BLOCKS) * 256 + threadIdx.x;
        int o  = gch / (KTOT / 8);
        int ch = gch - o * (KTOT / 8);
        int k0 = ch * 8;
        __half h[8];
#pragma unroll
        for (int v = 0; v < 8; v++) {
            int k = k0 + v;
            int i = k / KPI;
            int j = k - i * KPI;
            float val = (j < GP1) ? coeffs[(size_t)o * (IN_SZ * GP1) + (size_t)i * GP1 + j]
                                  : bw[(size_t)o * IN_SZ + i];
            h[v] = __float2half_rn(val);
        }
        *(uint4*)(g_Cmat + (size_t)o * KTOT + k0) = *(const uint4*)h;
    }
}

// ---------------------------------------------------------------------------
// Main GEMM: 256 CTAs (64 b x 4 o), CTA tile 128x128, 8 warps (256 thr),
// warp tile 64x32.  Stage K=64, double buffered, one barrier per stage.
// SMEM: A[2][16KB] @0, B[2][16KB] @32768, P-ring[2][4KB] @65536 -> 72KB,
// 2 CTAs/SM.  Producer work evenly split across all 256 threads.
// ---------------------------------------------------------------------------
#define A_REG  0
#define B_REG  32768
#define P_REG  65536
#define SMEM_SZ 73728

// genA half-row: thread handles row (tid&127), k-half (tid>>7): 32 slots=64B.
// Zero 4x16B, then predicated scatter of each overlapping feature's 3 halves.
__device__ __forceinline__ void genA(char* smem, int buf, int stage, int tid) {
    const int row  = tid & 127;
    const int half = tid >> 7;
    char* tile = smem + A_REG + buf * 16384;
    const char* pr = smem + P_REG + (stage & 1) * 4096;
    const uint32_t rowbase = (uint32_t)row * 128;
    const uint32_t hbase   = rowbase + (uint32_t)half * 64;
    uint4 z = make_uint4(0, 0, 0, 0);
#pragma unroll
    for (int c = 0; c < 4; c++)
        *(uint4*)(tile + sw128(hbase + c * 16)) = z;

    const int k0   = stage * 64;
    const int i_lo = k0 / KPI;
    const int w0   = half * 32;           // this thread's slot window [w0, w0+32)
#pragma unroll
    for (int f = 0; f < 4; f++) {
        int i = i_lo + f;
        if (i < IN_SZ) {
            float2 pv = *(const float2*)(pr + f * 1024 + row * 8);   // LDS.64
            int idx = (int)pv.y;                             // u >= 0
            idx = idx > 19 ? 19 : idx;                       // u==20 -> idx=19, t=1
            float t = pv.y - (float)idx;
            int kbase = i * KPI - k0;                        // stage-local slot 0
            int k1 = kbase + idx;                            // 1-t
            int k2 = k1 + 1;                                 // t
            int k3 = kbase + 21;                             // silu
            if ((unsigned)(k1 - w0) < 32u)
                *(__half*)(tile + sw128(rowbase + (uint32_t)k1 * 2)) = __float2half_rn(1.0f - t);
            if ((unsigned)(k2 - w0) < 32u)
                *(__half*)(tile + sw128(rowbase + (uint32_t)k2 * 2)) = __float2half_rn(t);
            if ((unsigned)(k3 - w0) < 32u)
                *(__half*)(tile + sw128(rowbase + (uint32_t)k3 * 2)) = __float2half_rn(pv.x);
        }
    }
}

// loadB: all 256 threads, 4 cp.async of 16B each (1024 chunks total).
__device__ __forceinline__ void loadB(uint32_t sb, int buf, int stage, int ob, int tid) {
    const int k0 = stage * 64;
#pragma unroll
    for (int rep = 0; rep < 4; rep++) {
        int q = tid + rep * 256;
        int r = q >> 3;
        int c = q & 7;
        const __half* gp = g_Cmat + (size_t)(ob + r) * KTOT + (k0 + c * 8);
        uint32_t sa = sb + B_REG + buf * 16384 + sw128((uint32_t)r * 128 + (uint32_t)c * 16);
        asm volatile("cp.async.cg.shared.global [%0], [%1], 16;" :: "r"(sa), "l"(gp));
    }
}

// loadP: all 256 threads, 1 cp.async of 16B (4 features x 128 float2 = 4KB).
__device__ __forceinline__ void loadP(uint32_t sb, int stage, int bb, int tid) {
    const int i_lo = (stage * 64) / KPI;
    const int f = tid >> 6;              // feature 0..3
    const int w = tid & 63;              // 16B unit within feature
    const int i = i_lo + f;
    if (i < IN_SZ) {
        const float2* gp = g_P + (size_t)i * B_SZ + bb + w * 2;
        uint32_t sa = sb + P_REG + (uint32_t)(stage & 1) * 4096
                    + (uint32_t)f * 1024 + (uint32_t)w * 16;
        asm volatile("cp.async.cg.shared.global [%0], [%1], 16;" :: "r"(sa), "l"(gp));
    }
}

__global__ __launch_bounds__(256, 2) void kan_main(float* __restrict__ out) {
    extern __shared__ char smem[];
    uint32_t sb = smem_u32(smem);
    const int tid   = threadIdx.x;
    const int lane  = tid & 31;
    const int wid   = tid >> 5;
    const int warpM = wid >> 2;             // 0..1 -> 64-row b stripe
    const int warpN = wid & 3;              // 0..3 -> 32-col o stripe
    const int ob = blockIdx.x * 128, bb = blockIdx.y * 128;

    float acc[4][4][4];
#pragma unroll
    for (int mt = 0; mt < 4; mt++)
#pragma unroll
        for (int nt = 0; nt < 4; nt++)
#pragma unroll
            for (int v = 0; v < 4; v++) acc[mt][nt][v] = 0.f;

    const uint32_t lrow = lane & 15;
    const uint32_t lkb  = (lane >> 4) * 16;

    // prologue: P(0), P(1), B(0) in flight; then genA(0).
    loadP(sb, 0, bb, tid);
    loadP(sb, 1, bb, tid);
    loadB(sb, 0, 0, ob, tid);
    asm volatile("cp.async.commit_group;");
    asm volatile("cp.async.wait_group 0;");
    __syncthreads();                              // P(0) visible
    genA(smem, 0, 0, tid);

    for (int s = 0; s < STAGES; s++) {
        const int cb = s & 1, nb = cb ^ 1;

        asm volatile("cp.async.wait_group 0;");   // B(s) + P(s+1) complete
        __syncthreads();                          // visible; nb reads (s-1) done

        if (s + 1 < STAGES) {                     // all threads produce next stage
            genA(smem, nb, s + 1, tid);
            loadB(sb, nb, s + 1, ob, tid);
            if (s + 2 < STAGES) loadP(sb, s + 2, bb, tid);
            asm volatile("cp.async.commit_group;");
        }

        const uint32_t Ab = sb + A_REG + cb * 16384;
        const uint32_t Bb = sb + B_REG + cb * 16384;
#pragma unroll
        for (int ks = 0; ks < 4; ks++) {
            uint32_t a[4][4];
#pragma unroll
            for (int mt = 0; mt < 4; mt++) {
                uint32_t row = (uint32_t)(warpM * 64 + mt * 16) + lrow;
                ldsm_x4(Ab + sw128(row * 128 + ks * 32 + lkb), a[mt]);
            }
            uint32_t bf[2][4];
#pragma unroll
            for (int bt = 0; bt < 2; bt++) {
                uint32_t nrow = (uint32_t)(warpN * 32 + bt * 16) + lrow;
                ldsm_x4(Bb + sw128(nrow * 128 + ks * 32 + lkb), bf[bt]);
            }
#pragma unroll
            for (int mt = 0; mt < 4; mt++)
#pragma unroll
                for (int nt = 0; nt < 4; nt++) {
                    int bt = nt >> 1, hi = nt & 1;
                    mma16816(acc[mt][nt], a[mt], bf[bt][hi], bf[bt][hi + 2]);
                }
        }
    }

    // epilogue: direct f32 stores
#pragma unroll
    for (int mt = 0; mt < 4; mt++) {
        int r0 = bb + warpM * 64 + mt * 16 + (lane >> 2);
#pragma unroll
        for (int nt = 0; nt < 4; nt++) {
            int c0 = ob + warpN * 32 + nt * 8 + (lane & 3) * 2;
            *(float2*)&out[(size_t)r0 * OUT_SZ + c0] =
                make_float2(acc[mt][nt][0], acc[mt][nt][1]);
            *(float2*)&out[(size_t)(r0 + 8) * OUT_SZ + c0] =
                make_float2(acc[mt][nt][2], acc[mt][nt][3]);
        }
    }
}

// ---------------------------------------------------------------------------
// Launch: x [8192,512], coeffs [512,512,21], base_w [512,512] -> out f32 [8192,512]
// ---------------------------------------------------------------------------
extern "C" void kernel_launch(void* const* d_in, const int* in_sizes, int n_in,
                              void* d_out, int out_size) {
    const float* x      = (const float*)d_in[0];
    const float* coeffs = (const float*)d_in[1];
    const float* base_w = (const float*)d_in[2];
    float* out = (float*)d_out;

    cudaFuncSetAttribute(kan_main, cudaFuncAttributeMaxDynamicSharedMemorySize, SMEM_SZ);

    kan_prep<<<PARAM_BLOCKS + CMAT_BLOCKS, 256>>>(x, coeffs, base_w);
    kan_main<<<dim3(OUT_SZ / 128, B_SZ / 128), 256, SMEM_SZ>>>(out);
}